// round 6
// baseline (speedup 1.0000x reference)
#include <cuda_runtime.h>
#include <cstddef>

// Problem shape (fixed by reference): x[1, 32, 256, 256, 8] float32
constexpr int D_ = 32;
constexpr int H_ = 256;
constexpr int W_ = 256;
constexpr int C_ = 8;
constexpr int TW = 16;   // w-strip per thread: fine granularity kills wave tail

// ---------------------------------------------------------------------------
// Hard compare-exchange (2x FMNMX, ALU pipe).
// ---------------------------------------------------------------------------
__device__ __forceinline__ void ce(float a, float b, float& mn, float& mx) {
    mn = fminf(a, b);
    mx = fmaxf(a, b);
}

// ---------------------------------------------------------------------------
// Generalized Batcher odd-even merge of two sorted lists (arbitrary M, N).
// Unused outputs are dead-code eliminated (exploited for truncated selection).
// ---------------------------------------------------------------------------
template <int M, int N>
__device__ __forceinline__ void omerge(const float* A, const float* B, float* R) {
    if constexpr (M == 0) {
#pragma unroll
        for (int i = 0; i < N; ++i) R[i] = B[i];
    } else if constexpr (N == 0) {
#pragma unroll
        for (int i = 0; i < M; ++i) R[i] = A[i];
    } else if constexpr (M == 1 && N == 1) {
        ce(A[0], B[0], R[0], R[1]);
    } else {
        constexpr int ME = (M + 1) / 2, MO = M / 2;
        constexpr int NE = (N + 1) / 2, NO = N / 2;
        float Ae[ME], Be[NE];
        float Ao[MO > 0 ? MO : 1], Bo[NO > 0 ? NO : 1];
#pragma unroll
        for (int i = 0; i < ME; ++i) Ae[i] = A[2 * i];
#pragma unroll
        for (int i = 0; i < MO; ++i) Ao[i] = A[2 * i + 1];
#pragma unroll
        for (int i = 0; i < NE; ++i) Be[i] = B[2 * i];
#pragma unroll
        for (int i = 0; i < NO; ++i) Bo[i] = B[2 * i + 1];

        constexpr int ES = ME + NE, OS = MO + NO;
        float E[ES], O[OS > 0 ? OS : 1];
        omerge<ME, NE>(Ae, Be, E);
        omerge<MO, NO>(Ao, Bo, O);

        R[0] = E[0];
#pragma unroll
        for (int i = 0; i < OS; ++i) {
            if (i + 1 < ES) {
                ce(O[i], E[i + 1], R[2 * i + 1], R[2 * i + 2]);
            } else {
                R[2 * i + 1] = O[i];
            }
        }
        if constexpr (ES == OS + 2) R[M + N - 1] = E[ES - 1];
    }
}

template <int N>
__device__ __forceinline__ void nsort(float* A) {
    if constexpr (N > 1) {
        constexpr int L = N / 2;
        nsort<L>(A);
        nsort<N - L>(A + L);
        float R[N];
        omerge<L, N - L>(A, A + L, R);
#pragma unroll
        for (int i = 0; i < N; ++i) A[i] = R[i];
    }
}

// jnp.pad mode="reflect": -1 -> 1, n -> n-2
__device__ __forceinline__ int refl(int i, int n) {
    i = (i < 0) ? -i : i;
    i = (i >= n) ? (2 * n - 2 - i) : i;
    return i;
}

template <bool EDGE>
__device__ __forceinline__ void load_col(const float* const (&rp)[5], int wc, float (&Cv)[5]) {
    const int rw = EDGE ? refl(wc, W_) : wc;
    const int off = rw * C_;
#pragma unroll
    for (int i = 0; i < 5; ++i) Cv[i] = __ldg(rp[i] + off);
}

// One sliding step producing the median at output column w.
//   PL = P_{w-2} = merge(col_{w-2}, col_{w-1})   (sorted 10)
//   PR = P_{w}   = merge(col_{w},   col_{w+1})   (sorted 10)
//   Cold = sorted col_{w+1};  loads col_{w+2} into Cnew, emits PO = P_{w+1}.
// Median(25) = rank-13 of PL ∪ PR ∪ col_{w+2}: only ranks 8..13 of the
// merged 20 can be the global median; final rank-6 of 6∪5 via the two-list
// minimax identity (min over splits of pairwise max).
template <bool EDGE>
__device__ __forceinline__ float med_step(
    const float* const (&rp)[5], int wc,
    const float (&PL)[10], const float (&PR)[10], float (&PO)[10],
    const float (&Cold)[5], float (&Cnew)[5]) {
    load_col<EDGE>(rp, wc, Cnew);
    nsort<5>(Cnew);
    omerge<5, 5>(Cold, Cnew, PO);   // P_{w+1}, reused by outputs w+1 and w+3

    float Z[20];
    omerge<10, 10>(PL, PR, Z);      // truncated: only Z[7..12] survive DCE

    float m;
    m = fminf(fmaxf(Z[7],  Cnew[4]),
        fminf(fmaxf(Z[8],  Cnew[3]),
        fminf(fmaxf(Z[9],  Cnew[2]),
        fminf(fmaxf(Z[10], Cnew[1]),
        fminf(fmaxf(Z[11], Cnew[0]), Z[12])))));
    return m;
}

template <bool EDGE>
__device__ __forceinline__ void run_strip(const float* const (&rp)[5], int t0, float* out) {
    // Pipeline state: ring of 4 pair-merges + 2 alternating sorted columns.
    float PA[10], PB[10], PC[10], PD[10];
    float Ca[5], Cb[5];
    {
        float c0[5], c1[5], c2[5];
        load_col<EDGE>(rp, t0 - 2, c0); nsort<5>(c0);
        load_col<EDGE>(rp, t0 - 1, c1); nsort<5>(c1);
        load_col<EDGE>(rp, t0,     c2); nsort<5>(c2);
        load_col<EDGE>(rp, t0 + 1, Ca); nsort<5>(Ca);
        omerge<5, 5>(c0, c1, PA);  // P_{t0-2}
        omerge<5, 5>(c1, c2, PB);  // P_{t0-1}
        omerge<5, 5>(c2, Ca, PC);  // P_{t0}
    }

    // 4-phase ring rotation: at output w the roles are
    //   (PL, PR, PO) = (P_{w-2}, P_w, P_{w+1}); Cold = col_{w+1}.
#pragma unroll 1
    for (int w = 0; w < TW; w += 4) {
        out[(w + 0) * C_] = med_step<EDGE>(rp, t0 + w + 2, PA, PC, PD, Ca, Cb);
        out[(w + 1) * C_] = med_step<EDGE>(rp, t0 + w + 3, PB, PD, PA, Cb, Ca);
        out[(w + 2) * C_] = med_step<EDGE>(rp, t0 + w + 4, PC, PA, PB, Ca, Cb);
        out[(w + 3) * C_] = med_step<EDGE>(rp, t0 + w + 5, PD, PB, PC, Cb, Ca);
    }
}

__global__ void __launch_bounds__(64, 16)
median5x5_kernel(const float* __restrict__ x, float* __restrict__ y) {
    const int bid = blockIdx.x;
    const int wt = bid & 15;         // 16 w-tiles of 16
    const int ht = (bid >> 4) & 31;  // 32 h-tiles of 8
    const int d  = bid >> 9;         // 32 depth slices
    const int c  = threadIdx.x & 7;  // channel (contiguous for coalescing)
    const int h  = ht * 8 + (threadIdx.x >> 3);
    const int t0 = wt * TW;

    const float* base = x + (size_t)d * (H_ * W_ * C_) + c;
    const float* rp[5];
#pragma unroll
    for (int i = 0; i < 5; ++i) {
        const int rh = refl(h - 2 + i, H_);
        rp[i] = base + (size_t)rh * (W_ * C_);
    }
    float* out = y + (((size_t)d * H_ + h) * W_ + t0) * C_ + c;

    // Interior w-tiles (wt 1..14): wc range [14,241] needs no reflection.
    if (wt == 0 || wt == 15) {
        run_strip<true>(rp, t0, out);
    } else {
        run_strip<false>(rp, t0, out);
    }
}

extern "C" void kernel_launch(void* const* d_in, const int* in_sizes, int n_in,
                              void* d_out, int out_size) {
    const float* x = (const float*)d_in[0];
    float* y = (float*)d_out;
    // grid: 32 d * 32 h-tiles * 16 w-tiles = 16384 blocks of 64 threads
    median5x5_kernel<<<16384, 64>>>(x, y);
}

// round 7
// speedup vs baseline: 1.1364x; 1.1364x over previous
#include <cuda_runtime.h>
#include <cstddef>

// Problem shape (fixed by reference): x[1, 32, 256, 256, 8] float32
constexpr int D_ = 32;
constexpr int H_ = 256;
constexpr int W_ = 256;
constexpr int C_ = 8;
constexpr int TW = 32;   // w-strip per thread (best config from R3)

// ---------------------------------------------------------------------------
// Compare-exchange.
// Hard: 2x FMNMX (alu pipe), depth 1.
// Soft (sum trick): s = a+b; mn = min(a,b); mx = s-mn.
//   s and mn are computed in parallel (depth 2 total). Both fma-pipe ops are
//   emitted as FFMA with float IMMEDIATE multiplier (0x823 imm-form,
//   rt_SMSP=1 -> 2x throughput vs 3-reg FFMA/FADD). Net per CE:
//   1 alu instr (was 2) + 2 cheap fma instrs. Error <= ~2 ulp (<< 1e-3).
// ---------------------------------------------------------------------------
template <bool SOFT>
__device__ __forceinline__ void ce(float a, float b, float& mn, float& mx) {
    if constexpr (SOFT) {
        float s;
        asm("fma.rn.f32 %0, %1, 0f3F800000, %2;" : "=f"(s) : "f"(a), "f"(b));   // s = a*1 + b
        mn = fminf(a, b);                                                        // FMNMX (alu)
        asm("fma.rn.f32 %0, %1, 0fBF800000, %2;" : "=f"(mx) : "f"(mn), "f"(s)); // mx = s - mn
    } else {
        mn = fminf(a, b);
        mx = fmaxf(a, b);
    }
}

// ---------------------------------------------------------------------------
// Generalized Batcher odd-even merge of two sorted lists (arbitrary M, N).
// Unused outputs are dead-code eliminated (exploited for truncated selection).
// ---------------------------------------------------------------------------
template <int M, int N, bool SOFT>
__device__ __forceinline__ void omerge(const float* A, const float* B, float* R) {
    if constexpr (M == 0) {
#pragma unroll
        for (int i = 0; i < N; ++i) R[i] = B[i];
    } else if constexpr (N == 0) {
#pragma unroll
        for (int i = 0; i < M; ++i) R[i] = A[i];
    } else if constexpr (M == 1 && N == 1) {
        ce<SOFT>(A[0], B[0], R[0], R[1]);
    } else {
        constexpr int ME = (M + 1) / 2, MO = M / 2;
        constexpr int NE = (N + 1) / 2, NO = N / 2;
        float Ae[ME], Be[NE];
        float Ao[MO > 0 ? MO : 1], Bo[NO > 0 ? NO : 1];
#pragma unroll
        for (int i = 0; i < ME; ++i) Ae[i] = A[2 * i];
#pragma unroll
        for (int i = 0; i < MO; ++i) Ao[i] = A[2 * i + 1];
#pragma unroll
        for (int i = 0; i < NE; ++i) Be[i] = B[2 * i];
#pragma unroll
        for (int i = 0; i < NO; ++i) Bo[i] = B[2 * i + 1];

        constexpr int ES = ME + NE, OS = MO + NO;
        float E[ES], O[OS > 0 ? OS : 1];
        omerge<ME, NE, SOFT>(Ae, Be, E);
        omerge<MO, NO, SOFT>(Ao, Bo, O);

        R[0] = E[0];
#pragma unroll
        for (int i = 0; i < OS; ++i) {
            if (i + 1 < ES) {
                ce<SOFT>(O[i], E[i + 1], R[2 * i + 1], R[2 * i + 2]);
            } else {
                R[2 * i + 1] = O[i];
            }
        }
        if constexpr (ES == OS + 2) R[M + N - 1] = E[ES - 1];
    }
}

template <int N, bool SOFT>
__device__ __forceinline__ void nsort(float* A) {
    if constexpr (N > 1) {
        constexpr int L = N / 2;
        nsort<L, SOFT>(A);
        nsort<N - L, SOFT>(A + L);
        float R[N];
        omerge<L, N - L, SOFT>(A, A + L, R);
#pragma unroll
        for (int i = 0; i < N; ++i) A[i] = R[i];
    }
}

// jnp.pad mode="reflect": -1 -> 1, n -> n-2
__device__ __forceinline__ int refl(int i, int n) {
    i = (i < 0) ? -i : i;
    i = (i >= n) ? (2 * n - 2 - i) : i;
    return i;
}

template <bool EDGE>
__device__ __forceinline__ void load_col(const float* const (&rp)[5], int wc, float (&Cv)[5]) {
    const int rw = EDGE ? refl(wc, W_) : wc;
    const int off = rw * C_;
#pragma unroll
    for (int i = 0; i < 5; ++i) Cv[i] = __ldg(rp[i] + off);
}

// One sliding step producing the median at output column w.
//   PL = P_{w-2} = merge(col_{w-2}, col_{w-1})   (sorted 10)
//   PR = P_{w}   = merge(col_{w},   col_{w+1})   (sorted 10)
//   Cold = sorted col_{w+1};  loads col_{w+2} into Cnew, emits PO = P_{w+1}.
// Median(25) = rank-13 of PL ∪ PR ∪ col_{w+2}: only ranks 8..13 of the
// merged 20 can be the global median; final rank-6 of 6∪5 via the two-list
// minimax identity (min over splits of pairwise max).
// Soft CEs in sort5 + pair merge (dual-output CEs); truncated merge and
// minimax stay hard (mostly single-output -> already 1 FMNMX each).
template <bool EDGE>
__device__ __forceinline__ float med_step(
    const float* const (&rp)[5], int wc,
    const float (&PL)[10], const float (&PR)[10], float (&PO)[10],
    const float (&Cold)[5], float (&Cnew)[5]) {
    load_col<EDGE>(rp, wc, Cnew);
    nsort<5, true>(Cnew);
    omerge<5, 5, true>(Cold, Cnew, PO);   // P_{w+1}, reused at w+1 and w+3

    float Z[20];
    omerge<10, 10, false>(PL, PR, Z);     // truncated: only Z[7..12] survive DCE

    float m;
    m = fminf(fmaxf(Z[7],  Cnew[4]),
        fminf(fmaxf(Z[8],  Cnew[3]),
        fminf(fmaxf(Z[9],  Cnew[2]),
        fminf(fmaxf(Z[10], Cnew[1]),
        fminf(fmaxf(Z[11], Cnew[0]), Z[12])))));
    return m;
}

template <bool EDGE>
__device__ __forceinline__ void run_strip(const float* const (&rp)[5], int t0, float* out) {
    // Pipeline state: ring of 4 pair-merges + 2 alternating sorted columns.
    float PA[10], PB[10], PC[10], PD[10];
    float Ca[5], Cb[5];
    {
        float c0[5], c1[5], c2[5];
        load_col<EDGE>(rp, t0 - 2, c0); nsort<5, true>(c0);
        load_col<EDGE>(rp, t0 - 1, c1); nsort<5, true>(c1);
        load_col<EDGE>(rp, t0,     c2); nsort<5, true>(c2);
        load_col<EDGE>(rp, t0 + 1, Ca); nsort<5, true>(Ca);
        omerge<5, 5, true>(c0, c1, PA);  // P_{t0-2}
        omerge<5, 5, true>(c1, c2, PB);  // P_{t0-1}
        omerge<5, 5, true>(c2, Ca, PC);  // P_{t0}
    }

    // 4-phase ring rotation: at output w the roles are
    //   (PL, PR, PO) = (P_{w-2}, P_w, P_{w+1}); Cold = col_{w+1}.
#pragma unroll 1
    for (int w = 0; w < TW; w += 4) {
        out[(w + 0) * C_] = med_step<EDGE>(rp, t0 + w + 2, PA, PC, PD, Ca, Cb);
        out[(w + 1) * C_] = med_step<EDGE>(rp, t0 + w + 3, PB, PD, PA, Cb, Ca);
        out[(w + 2) * C_] = med_step<EDGE>(rp, t0 + w + 4, PC, PA, PB, Ca, Cb);
        out[(w + 3) * C_] = med_step<EDGE>(rp, t0 + w + 5, PD, PB, PC, Cb, Ca);
    }
}

__global__ void __launch_bounds__(64, 14)
median5x5_kernel(const float* __restrict__ x, float* __restrict__ y) {
    const int bid = blockIdx.x;
    const int wt = bid & 7;          // 8 w-tiles of 32
    const int ht = (bid >> 3) & 31;  // 32 h-tiles of 8
    const int d  = bid >> 8;         // 32 depth slices
    const int c  = threadIdx.x & 7;  // channel (contiguous for coalescing)
    const int h  = ht * 8 + (threadIdx.x >> 3);
    const int t0 = wt * TW;

    const float* base = x + (size_t)d * (H_ * W_ * C_) + c;
    const float* rp[5];
#pragma unroll
    for (int i = 0; i < 5; ++i) {
        const int rh = refl(h - 2 + i, H_);
        rp[i] = base + (size_t)rh * (W_ * C_);
    }
    float* out = y + (((size_t)d * H_ + h) * W_ + t0) * C_ + c;

    // Interior w-tiles (wt 1..6): wc range [30,225] needs no reflection.
    if (wt == 0 || wt == 7) {
        run_strip<true>(rp, t0, out);
    } else {
        run_strip<false>(rp, t0, out);
    }
}

extern "C" void kernel_launch(void* const* d_in, const int* in_sizes, int n_in,
                              void* d_out, int out_size) {
    const float* x = (const float*)d_in[0];
    float* y = (float*)d_out;
    // grid: 32 d * 32 h-tiles * 8 w-tiles = 8192 blocks of 64 threads
    median5x5_kernel<<<8192, 64>>>(x, y);
}